// round 7
// baseline (speedup 1.0000x reference)
#include <cuda_runtime.h>

// RALoss fused: loss = sum_i mean_j 10*exp(-sum_{hw}(amax[i,j,hw]-aorg[i,j,hw]))
// Shapes: (4, 64, 512, 512) fp32 x2, scalar fp32 out.
// Flat decomposition: 1184 = 148 SMs x 8 blocks, one perfectly balanced wave.
// Each block: contiguous 14171-float4 chunk (spans <= 2 pairs), float2 partial.
// acq_rel atomic signaling, last-block finalize (fixed-order -> deterministic).

#define PAIRS 256
#define HW (512 * 512)                 // 262144 elems per pair
#define PAIR_F4 (HW / 4)               // 65536 float4 per pair (= 1<<16)
#define TOTAL_F4 (PAIRS * PAIR_F4)     // 16,777,216 float4
#define GRID_TOTAL 1184                // 148 * 8 : one full wave
#define THREADS 256
#define CHUNK 14171u                   // ceil(TOTAL_F4 / GRID_TOTAL)
#define PT_ITERS 56                    // ceil(CHUNK / THREADS)

__device__ float2 g_part[GRID_TOTAL];
__device__ unsigned int g_done_count;  // zero-init at load; reset each replay

__global__ __launch_bounds__(THREADS, 8)
void raloss_fused_kernel(const float4* __restrict__ amax,
                         const float4* __restrict__ aorg,
                         float* __restrict__ out) {
    const unsigned int bid = blockIdx.x;
    const unsigned int tid = threadIdx.x;
    const unsigned int warp = tid >> 5;
    const unsigned int lane = tid & 31;

    const unsigned int start = bid * CHUNK;
    const unsigned int end   = min(start + CHUNK, (unsigned int)TOTAL_F4);
    const unsigned int fp    = start >> 16;          // first pair this block touches
    const unsigned int bound = (fp + 1u) << 16;      // f4 index where next pair begins

    float a0 = 0.0f, a1 = 0.0f;   // partial for pair fp / pair fp+1

#pragma unroll 2
    for (int it = 0; it < PT_ITERS; it++) {
        unsigned int idx = start + (unsigned int)it * THREADS + tid;
        if (idx < end) {
            float4 ma = __ldcs(&amax[idx]);
            float4 mo = __ldcs(&aorg[idx]);
            float d = (ma.x - mo.x) + (ma.y - mo.y) + (ma.z - mo.z) + (ma.w - mo.w);
            if (idx < bound) a0 += d; else a1 += d;
        }
    }

    // Warp reduce both accumulators
#pragma unroll
    for (int off = 16; off > 0; off >>= 1) {
        a0 += __shfl_xor_sync(0xFFFFFFFFu, a0, off);
        a1 += __shfl_xor_sync(0xFFFFFFFFu, a1, off);
    }

    __shared__ float ws0[THREADS / 32];
    __shared__ float ws1[THREADS / 32];
    __shared__ bool  s_is_last;
    if (lane == 0) { ws0[warp] = a0; ws1[warp] = a1; }
    __syncthreads();

    if (warp == 0) {
        float v0 = (lane < (THREADS / 32)) ? ws0[lane] : 0.0f;
        float v1 = (lane < (THREADS / 32)) ? ws1[lane] : 0.0f;
#pragma unroll
        for (int off = 4; off > 0; off >>= 1) {
            v0 += __shfl_xor_sync(0xFFFFFFFFu, v0, off);
            v1 += __shfl_xor_sync(0xFFFFFFFFu, v1, off);
        }
        if (lane == 0) {
            g_part[bid] = make_float2(v0, v1);
            // acq_rel atomic: release publishes g_part[bid]; acquire (for the
            // winner) makes every other block's released partial visible.
            unsigned int old;
            asm volatile("atom.acq_rel.gpu.global.add.u32 %0, [%1], %2;"
                         : "=r"(old)
                         : "l"(&g_done_count), "r"(1u)
                         : "memory");
            s_is_last = (old == (unsigned int)(GRID_TOTAL - 1));
        }
    }
    __syncthreads();

    // ---- Last block finalizes ----
    if (s_is_last) {
        const unsigned int p = tid;   // pair id, 0..255

        // Blocks whose chunk intersects pair p: [b_first, b_last], <= 6 blocks.
        const unsigned int b_first = (p << 16) / CHUNK;          // contains pair start
        const unsigned int b_last  = min((unsigned int)(GRID_TOTAL - 1),
                                         (((p + 1u) << 16) - 1u) / CHUNK);

        float d = 0.0f;
        for (unsigned int b = b_first; b <= b_last; b++) {
            float2 pp;
            pp.x = __ldcg(&g_part[b].x);
            pp.y = __ldcg(&g_part[b].y);
            unsigned int bfp = (b * CHUNK) >> 16;
            if (bfp == p)           d += pp.x;
            else if (bfp + 1u == p) d += pp.y;
        }

        // contribution: 10*exp(-d)/64  (sum_i mean_j == sum over 256 pairs / 64)
        float v = 10.0f * expf(-d) * (1.0f / 64.0f);

#pragma unroll
        for (int off = 16; off > 0; off >>= 1)
            v += __shfl_xor_sync(0xFFFFFFFFu, v, off);

        if (lane == 0) ws0[warp] = v;
        __syncthreads();

        if (warp == 0) {
            float w = (lane < (THREADS / 32)) ? ws0[lane] : 0.0f;
#pragma unroll
            for (int off = 4; off > 0; off >>= 1)
                w += __shfl_xor_sync(0xFFFFFFFFu, w, off);
            if (lane == 0) {
                out[0] = w;
                g_done_count = 0;   // reset for next graph replay
            }
        }
    }
}

extern "C" void kernel_launch(void* const* d_in, const int* in_sizes, int n_in,
                              void* d_out, int out_size) {
    const float4* amax = (const float4*)d_in[0];
    const float4* aorg = (const float4*)d_in[1];
    float* out = (float*)d_out;

    raloss_fused_kernel<<<GRID_TOTAL, THREADS>>>(amax, aorg, out);
}